// round 16
// baseline (speedup 1.0000x reference)
#include <cuda_runtime.h>
#include <cuda_bf16.h>
#include <math.h>
#include <stdint.h>

#define B_N   8192
#define DIN   256
#define DE    128
#define NEX   16384
#define NDUR  64
#define NSPLIT 2
#define GAMMA_N 3.6787944117144233e-06f   // exp(-1)/100000

// ---------------- device scratch ----------------
__device__ __align__(16) __nv_bfloat16 g_phiB[B_N * DE];   // bf16(-2*phi) [B][128]
__device__ __align__(16) __nv_bfloat16 g_EB[NEX * DE];     // bf16(E)      [NEX][128]
__device__ __align__(16) __nv_bfloat16 g_KMTB[NDUR * NEX]; // bf16(KM^T)   [64][NEX]
__device__ __align__(16) float g_pn[B_N];                  // ||phi||^2
__device__ __align__(16) float g_en[NEX];                  // ||E||^2
__device__ __align__(16) float g_pnum[NSPLIT * B_N * NDUR];
__device__ __align__(16) float g_pden[NSPLIT * B_N];

// ---------------- helpers ----------------
__device__ __forceinline__ void cp_async16(void* smem, const void* gmem) {
    unsigned sa = (unsigned)__cvta_generic_to_shared(smem);
    asm volatile("cp.async.cg.shared.global [%0], [%1], 16;" :: "r"(sa), "l"(gmem));
}
#define CP_COMMIT() asm volatile("cp.async.commit_group;" ::: "memory")
#define CP_WAIT0()  asm volatile("cp.async.wait_group 0;" ::: "memory")

__device__ __forceinline__ void mma_bf16(float& c0, float& c1, float& c2, float& c3,
                                         uint32_t a0, uint32_t a1, uint32_t a2, uint32_t a3,
                                         uint32_t b0, uint32_t b1) {
    asm volatile(
        "mma.sync.aligned.m16n8k16.row.col.f32.bf16.bf16.f32 "
        "{%0,%1,%2,%3}, {%4,%5,%6,%7}, {%8,%9}, {%0,%1,%2,%3};"
        : "+f"(c0), "+f"(c1), "+f"(c2), "+f"(c3)
        : "r"(a0), "r"(a1), "r"(a2), "r"(a3), "r"(b0), "r"(b1));
}
__device__ __forceinline__ uint32_t pack_bf16x2(float lo, float hi) {
    uint32_t r;
    asm("cvt.rn.bf16x2.f32 %0, %1, %2;" : "=r"(r) : "f"(hi), "f"(lo));
    return r;
}
__device__ __forceinline__ void ldmat4(uint32_t& r0, uint32_t& r1, uint32_t& r2, uint32_t& r3,
                                       uint32_t addr) {
    asm volatile("ldmatrix.sync.aligned.m8n8.x4.shared.b16 {%0,%1,%2,%3}, [%4];"
                 : "=r"(r0), "=r"(r1), "=r"(r2), "=r"(r3) : "r"(addr));
}

// ---------------- kernel 1: phi encoder -> g_phiB (bf16 -2phi), g_pn ----------------
__global__ void phi_pn_kernel(const float* __restrict__ x,
                              const float* __restrict__ W,
                              const float* __restrict__ bias) {
    __shared__ float xs[16 * DIN];
    __shared__ float pnred[16][4];
    const int tid = threadIdx.x;
    const int r0 = blockIdx.x * 16;

    const float4* xv = reinterpret_cast<const float4*>(x + r0 * DIN);
    float4* xsv = reinterpret_cast<float4*>(xs);
    #pragma unroll
    for (int i = 0; i < 8; ++i) xsv[tid + i * 128] = xv[tid + i * 128];
    const float bj = bias[tid];
    __syncthreads();

    float a[16];
    #pragma unroll
    for (int r = 0; r < 16; ++r) a[r] = 0.f;
    #pragma unroll 4
    for (int k = 0; k < DIN; ++k) {
        float w = W[k * DE + tid];
        #pragma unroll
        for (int r = 0; r < 16; ++r) a[r] += xs[r * DIN + k] * w;
    }
    #pragma unroll
    for (int r = 0; r < 16; ++r) {
        float v = a[r] + bj;
        g_phiB[(r0 + r) * DE + tid] = __float2bfloat16(-2.f * v);
        a[r] = v * v;
    }
    const int lane = tid & 31, warp = tid >> 5;
    #pragma unroll
    for (int r = 0; r < 16; ++r) {
        float v = a[r];
        #pragma unroll
        for (int o = 16; o; o >>= 1) v += __shfl_xor_sync(0xffffffffu, v, o);
        if (lane == 0) pnred[r][warp] = v;
    }
    __syncthreads();
    if (tid < 16)
        g_pn[r0 + tid] = pnred[tid][0] + pnred[tid][1] + pnred[tid][2] + pnred[tid][3];
}

// ---------------- kernel 2: en[n] = ||E_n||^2 and g_EB = bf16(E) ----------------
__global__ void en_eb_kernel(const float* __restrict__ E) {
    const int warp = threadIdx.x >> 5, lane = threadIdx.x & 31;
    const int row = blockIdx.x * 8 + warp;
    const float4* Ev = reinterpret_cast<const float4*>(E);
    float4 v = Ev[row * (DE / 4) + lane];
    uint2 pk;
    pk.x = pack_bf16x2(v.x, v.y);
    pk.y = pack_bf16x2(v.z, v.w);
    *reinterpret_cast<uint2*>(reinterpret_cast<char*>(g_EB) + row * 256 + lane * 8) = pk;
    float s = v.x * v.x + v.y * v.y + v.z * v.z + v.w * v.w;
    #pragma unroll
    for (int o = 16; o; o >>= 1) s += __shfl_xor_sync(0xffffffffu, s, o);
    if (lane == 0) g_en[row] = s;
}

// ---------------- kernel 3: KM curves -> g_KMTB bf16 [d][NEX] (fast-math) ----------------
__global__ void km_kernel(const float* __restrict__ lev,
                          const float* __restrict__ lcen) {
    __shared__ float buf[4][64];
    const int t = threadIdx.x, ty = threadIdx.y;
    const int row = blockIdx.x * 4 + ty;
    float ev = __expf(lev[row * NDUR + t]);
    float cn = __expf(lcen[row * NDUR + t]);
    float v = ev + cn;
    buf[ty][t] = v;
    #pragma unroll
    for (int off = 1; off < 64; off <<= 1) {
        __syncthreads();
        float add = (t + off < 64) ? buf[ty][t + off] : 0.f;
        __syncthreads();
        v += add;
        buf[ty][t] = v;
    }
    float at_risk = v;
    float hz = (at_risk > 0.f) ? (ev / at_risk) : 0.f;
    float lg = __logf(1.f - hz + 1e-7f);
    __syncthreads();
    buf[ty][t] = lg;
    float c = lg;
    #pragma unroll
    for (int off = 1; off < 64; off <<= 1) {
        __syncthreads();
        float add = (t >= off) ? buf[ty][t - off] : 0.f;
        __syncthreads();
        c += add;
        buf[ty][t] = c;
    }
    g_KMTB[t * NEX + row] = __float2bfloat16(__expf(c));
}

// ---------------- main mma.sync kernel (512 thr, s-split, A reg-cached) ----------------
// grid (64, 2), 512 threads = 16 warps = 8 m-groups x 2 s-halves. 1 CTA/SM.
// Warp (mw, s): GEMM1 m16 x n32 (s-half, K=128, A cached in regs),
//               GEMM2 partial numer[m16, d64] over K=32 (its n-half).
// s=1 partials merged into s=0 via smem (A-tile region, dead after frag-load).
#define SM_A    0
#define SM_E    34816
#define SM_KM   69632
#define SM_EN   88064
#define SM_BYTES 88576
#define PITCH_AB 272
#define PITCH_K  144
#define NTILE    64
#define NT_CTA   (NEX / NSPLIT / NTILE)   // 128

__device__ __forceinline__ void prefetch_tile(char* smem, int nb, int buf, int tid) {
    // E: 64 rows x 16 chunks of 16B = 1024 chunks
    #pragma unroll
    for (int i = 0; i < 2; ++i) {
        int f = tid + i * 512;
        int n = f >> 4, c = f & 15;
        cp_async16(smem + SM_E + buf * 17408 + n * PITCH_AB + c * 16,
                   reinterpret_cast<const char*>(g_EB) + (nb + n) * 256 + c * 16);
    }
    // KM: 64 rows(d) x 8 chunks = 512 chunks
    {
        int d = tid >> 3, c = tid & 7;
        cp_async16(smem + SM_KM + buf * 9216 + d * PITCH_K + c * 16,
                   reinterpret_cast<const char*>(g_KMTB) + d * (NEX * 2) + nb * 2 + c * 16);
    }
    if (tid < 16)
        cp_async16(smem + SM_EN + buf * 256 + tid * 16, g_en + nb + tid * 4);
}

__global__ void __launch_bounds__(512, 1)
main_mma() {
    extern __shared__ __align__(16) char smem[];
    const uint32_t sbase = (uint32_t)__cvta_generic_to_shared(smem);
    const int tid = threadIdx.x;
    const int w = tid >> 5, lane = tid & 31;
    const int mw = w >> 1, s = w & 1;
    const int g = lane >> 2, tg = lane & 3;
    const int bm = blockIdx.x;
    const int split = blockIdx.y;
    const int nbase0 = split * (NEX / NSPLIT);

    const uint32_t a_lane = (uint32_t)((mw * 16 + ((lane >> 3) & 1) * 8 + (lane & 7)) * PITCH_AB
                                       + (lane >> 4) * 16);
    const uint32_t b_laneAB = (uint32_t)(((lane >> 4) * 8 + (lane & 7)) * PITCH_AB
                                         + ((lane >> 3) & 1) * 16);
    const uint32_t b_laneK  = (uint32_t)(((lane >> 4) * 8 + (lane & 7)) * PITCH_K
                                         + ((lane >> 3) & 1) * 16);

    // ---- prologue: A tile + tile 0 ----
    #pragma unroll
    for (int i = 0; i < 4; ++i) {
        int f = tid + i * 512;
        int m = f >> 4, c = f & 15;
        cp_async16(smem + SM_A + m * PITCH_AB + c * 16,
                   reinterpret_cast<const char*>(g_phiB) + (bm * 128 + m) * 256 + c * 16);
    }
    prefetch_tile(smem, nbase0, 0, tid);
    CP_COMMIT();
    CP_WAIT0();
    __syncthreads();

    // ---- cache A fragments in registers (reused for all tiles) ----
    uint32_t afr[8][4];
    {
        const uint32_t AsB = sbase + SM_A + a_lane;
        #pragma unroll
        for (int kk = 0; kk < 8; ++kk)
            ldmat4(afr[kk][0], afr[kk][1], afr[kk][2], afr[kk][3], AsB + kk * 32);
    }

    const float pnr0 = g_pn[bm * 128 + mw * 16 + g];
    const float pnr1 = g_pn[bm * 128 + mw * 16 + g + 8];

    float acc2[8][4];
    #pragma unroll
    for (int j = 0; j < 8; ++j)
        #pragma unroll
        for (int c = 0; c < 4; ++c) acc2[j][c] = 0.f;
    float dAcc0 = 0.f, dAcc1 = 0.f;

    for (int t = 0; t < NT_CTA; ++t) {
        const int buf = t & 1;
        if (t > 0) {
            CP_WAIT0();
            __syncthreads();
        }
        if (t + 1 < NT_CTA) {
            prefetch_tile(smem, nbase0 + (t + 1) * NTILE, buf ^ 1, tid);
            CP_COMMIT();
        }

        const uint32_t EsB = sbase + SM_E + buf * 17408 + b_laneAB
                           + (uint32_t)(s * 32) * PITCH_AB;
        const uint32_t MsB = sbase + SM_KM + buf * 9216 + b_laneK;
        const float* enb = reinterpret_cast<const float*>(smem + SM_EN + buf * 256) + s * 32;

        // ---- GEMM1: S = (-2phi) . E^T  (m16 x n32, K=128, A cached) ----
        float acc1[4][4];
        #pragma unroll
        for (int j = 0; j < 4; ++j)
            #pragma unroll
            for (int c = 0; c < 4; ++c) acc1[j][c] = 0.f;

        #pragma unroll
        for (int kk = 0; kk < 8; ++kk) {
            uint32_t b0, b1, b2, b3;
            ldmat4(b0, b1, b2, b3, EsB + kk * 32);                     // j=0,1
            uint32_t b4, b5, b6, b7;
            ldmat4(b4, b5, b6, b7, EsB + 16 * PITCH_AB + kk * 32);     // j=2,3
            mma_bf16(acc1[0][0], acc1[0][1], acc1[0][2], acc1[0][3],
                     afr[kk][0], afr[kk][1], afr[kk][2], afr[kk][3], b0, b1);
            mma_bf16(acc1[1][0], acc1[1][1], acc1[1][2], acc1[1][3],
                     afr[kk][0], afr[kk][1], afr[kk][2], afr[kk][3], b2, b3);
            mma_bf16(acc1[2][0], acc1[2][1], acc1[2][2], acc1[2][3],
                     afr[kk][0], afr[kk][1], afr[kk][2], afr[kk][3], b4, b5);
            mma_bf16(acc1[3][0], acc1[3][1], acc1[3][2], acc1[3][3],
                     afr[kk][0], afr[kk][1], afr[kk][2], afr[kk][3], b6, b7);
        }

        // ---- epilogue: kw = mask * exp(-d2) -> GEMM2 A-frags ----
        uint32_t kwreg[4][2];
        #pragma unroll
        for (int j = 0; j < 4; ++j) {
            float2 en2 = *reinterpret_cast<const float2*>(enb + j * 8 + 2 * tg);
            float d00 = fmaxf(pnr0 + en2.x + acc1[j][0], 0.f);
            float d01 = fmaxf(pnr0 + en2.y + acc1[j][1], 0.f);
            float d10 = fmaxf(pnr1 + en2.x + acc1[j][2], 0.f);
            float d11 = fmaxf(pnr1 + en2.y + acc1[j][3], 0.f);
            float k00 = (d00 <= 1.0f) ? __expf(-d00) : 0.f;
            float k01 = (d01 <= 1.0f) ? __expf(-d01) : 0.f;
            float k10 = (d10 <= 1.0f) ? __expf(-d10) : 0.f;
            float k11 = (d11 <= 1.0f) ? __expf(-d11) : 0.f;
            dAcc0 += k00 + k01;
            dAcc1 += k10 + k11;
            kwreg[j][0] = pack_bf16x2(k00, k01);
            kwreg[j][1] = pack_bf16x2(k10, k11);
        }

        // ---- GEMM2: partial numer += kw . KM  (m16 x d64, K=32 of this s-half) ----
        #pragma unroll
        for (int q = 0; q < 2; ++q) {
            const int kk2 = s * 2 + q;
            uint32_t b[8][2];
            #pragma unroll
            for (int bj = 0; bj < 4; ++bj)
                ldmat4(b[2 * bj][0], b[2 * bj][1], b[2 * bj + 1][0], b[2 * bj + 1][1],
                       MsB + bj * 16 * PITCH_K + kk2 * 32);
            const uint32_t a0 = kwreg[2 * q][0], a1 = kwreg[2 * q][1];
            const uint32_t a2 = kwreg[2 * q + 1][0], a3 = kwreg[2 * q + 1][1];
            #pragma unroll
            for (int j = 0; j < 8; ++j)
                mma_bf16(acc2[j][0], acc2[j][1], acc2[j][2], acc2[j][3],
                         a0, a1, a2, a3, b[j][0], b[j][1]);
        }
    }

    // ---- s-half merge via smem (A-tile region is dead) ----
    float* red = reinterpret_cast<float*>(smem + SM_A);
    // acc2: s=1 stores 32 floats per thread; denom 2 floats per thread at offset 32768B
    float* dred = reinterpret_cast<float*>(smem + SM_A + 32768);
    __syncthreads();   // all tile smem reads done before overwrite
    if (s == 1) {
        #pragma unroll
        for (int j = 0; j < 8; ++j) {
            *reinterpret_cast<float4*>(red + mw * 1024 + lane * 32 + j * 4)
                = make_float4(acc2[j][0], acc2[j][1], acc2[j][2], acc2[j][3]);
        }
        dred[mw * 64 + lane * 2 + 0] = dAcc0;
        dred[mw * 64 + lane * 2 + 1] = dAcc1;
    }
    __syncthreads();
    if (s == 0) {
        #pragma unroll
        for (int j = 0; j < 8; ++j) {
            float4 o = *reinterpret_cast<float4*>(red + mw * 1024 + lane * 32 + j * 4);
            acc2[j][0] += o.x; acc2[j][1] += o.y; acc2[j][2] += o.z; acc2[j][3] += o.w;
        }
        dAcc0 += dred[mw * 64 + lane * 2 + 0];
        dAcc1 += dred[mw * 64 + lane * 2 + 1];

        // ---- write numerators ----
        #pragma unroll
        for (int j = 0; j < 8; ++j) {
            const int m_loc = mw * 16 + g;
            const int d_loc = j * 8 + 2 * tg;
            float* dst = g_pnum + (size_t)(split * B_N + bm * 128 + m_loc) * NDUR + d_loc;
            *reinterpret_cast<float2*>(dst) = make_float2(acc2[j][0], acc2[j][1]);
            *reinterpret_cast<float2*>(dst + 8 * NDUR) = make_float2(acc2[j][2], acc2[j][3]);
        }

        // ---- denom: quad reduce ----
        dAcc0 += __shfl_xor_sync(0xffffffffu, dAcc0, 1);
        dAcc0 += __shfl_xor_sync(0xffffffffu, dAcc0, 2);
        dAcc1 += __shfl_xor_sync(0xffffffffu, dAcc1, 1);
        dAcc1 += __shfl_xor_sync(0xffffffffu, dAcc1, 2);
        if (tg == 0) {
            g_pden[split * B_N + bm * 128 + mw * 16 + g] = dAcc0;
            g_pden[split * B_N + bm * 128 + mw * 16 + g + 8] = dAcc1;
        }
    }
}

// ---------------- finalize (with inline baseline-hazard scan) ----------------
__global__ void __launch_bounds__(256)
finalize_kernel(float* __restrict__ out, const float* __restrict__ lh) {
    __shared__ float gb[64];
    const int tid = threadIdx.x;
    if (tid < 64) {
        float h = 1.f / (1.f + __expf(-lh[tid]));
        gb[tid] = __logf(1.f - h + 1e-7f);
    }
    float c = 0.f;
    #pragma unroll
    for (int off = 1; off < 64; off <<= 1) {
        __syncthreads();
        if (tid < 64) c = gb[tid] + ((tid >= off) ? gb[tid - off] : 0.f);
        __syncthreads();
        if (tid < 64) gb[tid] = c;
    }
    __syncthreads();
    const int idx = blockIdx.x * 256 + tid;
    const int b = idx >> 6, d = idx & 63;
    float num = GAMMA_N * __expf(gb[d]);
    float den = GAMMA_N + 1e-12f;
    #pragma unroll
    for (int s = 0; s < NSPLIT; ++s) {
        num += g_pnum[s * B_N * NDUR + idx];
        den += g_pden[s * B_N + b];
    }
    float r = num / den;
    r = fminf(fmaxf(r, 1e-12f), 1.0f - 1e-12f);
    out[idx] = r;
}

// ---------------- launch ----------------
extern "C" void kernel_launch(void* const* d_in, const int* in_sizes, int n_in,
                              void* d_out, int out_size) {
    const float* x    = (const float*)d_in[0];
    const float* W    = (const float*)d_in[1];
    const float* bias = (const float*)d_in[2];
    const float* E    = (const float*)d_in[3];
    const float* lev  = (const float*)d_in[4];
    const float* lcen = (const float*)d_in[5];
    const float* lh   = (const float*)d_in[6];
    float* out = (float*)d_out;

    static bool attr_set = false;
    if (!attr_set) {
        cudaFuncSetAttribute(main_mma,
                             cudaFuncAttributeMaxDynamicSharedMemorySize, SM_BYTES);
        attr_set = true;
    }

    phi_pn_kernel<<<B_N / 16, 128>>>(x, W, bias);
    en_eb_kernel<<<NEX / 8, 256>>>(E);
    km_kernel<<<NEX / 4, dim3(64, 4)>>>(lev, lcen);
    main_mma<<<dim3(B_N / 128, NSPLIT), 512, SM_BYTES>>>();
    finalize_kernel<<<(B_N * NDUR) / 256, 256>>>(out, lh);
}

// round 17
// speedup vs baseline: 1.0482x; 1.0482x over previous
#include <cuda_runtime.h>
#include <cuda_bf16.h>
#include <math.h>
#include <stdint.h>

#define B_N   8192
#define DIN   256
#define DE    128
#define NEX   16384
#define NDUR  64
#define NSPLIT 4
#define GAMMA_N 3.6787944117144233e-06f   // exp(-1)/100000
#define NEG_L2E (-1.4426950408889634f)

// ---------------- device scratch ----------------
__device__ __align__(16) __nv_bfloat16 g_phiB[B_N * DE];   // bf16(-2*phi) [B][128]
__device__ __align__(16) __nv_bfloat16 g_EB[NEX * DE];     // bf16(E)      [NEX][128]
__device__ __align__(16) __nv_bfloat16 g_KMTB[NDUR * NEX]; // bf16(KM^T)   [64][NEX]
__device__ __align__(16) float g_pn[B_N];                  // ||phi||^2
__device__ __align__(16) float g_en[NEX];                  // ||E||^2
__device__ __align__(16) float g_pnum[NSPLIT * B_N * NDUR];
__device__ __align__(16) float g_pden[NSPLIT * B_N];

// ---------------- helpers ----------------
__device__ __forceinline__ void cp_async16(void* smem, const void* gmem) {
    unsigned sa = (unsigned)__cvta_generic_to_shared(smem);
    asm volatile("cp.async.cg.shared.global [%0], [%1], 16;" :: "r"(sa), "l"(gmem));
}
#define CP_COMMIT() asm volatile("cp.async.commit_group;" ::: "memory")
#define CP_WAIT0()  asm volatile("cp.async.wait_group 0;" ::: "memory")

__device__ __forceinline__ void mma_bf16(float& c0, float& c1, float& c2, float& c3,
                                         uint32_t a0, uint32_t a1, uint32_t a2, uint32_t a3,
                                         uint32_t b0, uint32_t b1) {
    asm volatile(
        "mma.sync.aligned.m16n8k16.row.col.f32.bf16.bf16.f32 "
        "{%0,%1,%2,%3}, {%4,%5,%6,%7}, {%8,%9}, {%0,%1,%2,%3};"
        : "+f"(c0), "+f"(c1), "+f"(c2), "+f"(c3)
        : "r"(a0), "r"(a1), "r"(a2), "r"(a3), "r"(b0), "r"(b1));
}
__device__ __forceinline__ uint32_t pack_bf16x2(float lo, float hi) {
    uint32_t r;
    asm("cvt.rn.bf16x2.f32 %0, %1, %2;" : "=r"(r) : "f"(hi), "f"(lo));
    return r;
}
__device__ __forceinline__ float ex2f(float x) {
    float r;
    asm("ex2.approx.f32 %0, %1;" : "=f"(r) : "f"(x));
    return r;
}
__device__ __forceinline__ void ldmat4(uint32_t& r0, uint32_t& r1, uint32_t& r2, uint32_t& r3,
                                       uint32_t addr) {
    asm volatile("ldmatrix.sync.aligned.m8n8.x4.shared.b16 {%0,%1,%2,%3}, [%4];"
                 : "=r"(r0), "=r"(r1), "=r"(r2), "=r"(r3) : "r"(addr));
}

// ---------------- kernel 1: phi encoder -> g_phiB (bf16 -2phi), g_pn ----------------
__global__ void phi_pn_kernel(const float* __restrict__ x,
                              const float* __restrict__ W,
                              const float* __restrict__ bias) {
    __shared__ float xs[16 * DIN];
    __shared__ float pnred[16][4];
    const int tid = threadIdx.x;
    const int r0 = blockIdx.x * 16;

    const float4* xv = reinterpret_cast<const float4*>(x + r0 * DIN);
    float4* xsv = reinterpret_cast<float4*>(xs);
    #pragma unroll
    for (int i = 0; i < 8; ++i) xsv[tid + i * 128] = xv[tid + i * 128];
    const float bj = bias[tid];
    __syncthreads();

    float a[16];
    #pragma unroll
    for (int r = 0; r < 16; ++r) a[r] = 0.f;
    #pragma unroll 4
    for (int k = 0; k < DIN; ++k) {
        float w = W[k * DE + tid];
        #pragma unroll
        for (int r = 0; r < 16; ++r) a[r] += xs[r * DIN + k] * w;
    }
    #pragma unroll
    for (int r = 0; r < 16; ++r) {
        float v = a[r] + bj;
        g_phiB[(r0 + r) * DE + tid] = __float2bfloat16(-2.f * v);
        a[r] = v * v;
    }
    const int lane = tid & 31, warp = tid >> 5;
    #pragma unroll
    for (int r = 0; r < 16; ++r) {
        float v = a[r];
        #pragma unroll
        for (int o = 16; o; o >>= 1) v += __shfl_xor_sync(0xffffffffu, v, o);
        if (lane == 0) pnred[r][warp] = v;
    }
    __syncthreads();
    if (tid < 16)
        g_pn[r0 + tid] = pnred[tid][0] + pnred[tid][1] + pnred[tid][2] + pnred[tid][3];
}

// ---------------- kernel 2: merged en/EB + KM ----------------
// blocks [0, 64): KM curves, thread-per-row, register scans, no barriers
// blocks [64, 64+2048): en + bf16 E conversion
#define KM_BLOCKS 64
#define EN_BLOCKS (NEX / 8)

__global__ void __launch_bounds__(256)
enkm_kernel(const float* __restrict__ E,
            const float* __restrict__ lev,
            const float* __restrict__ lcen) {
    const int blk = blockIdx.x;
    const int tid = threadIdx.x;

    if (blk < KM_BLOCKS) {
        const int row = blk * 256 + tid;
        const float* pe = lev + row * NDUR;
        const float* pc = lcen + row * NDUR;
        float lg[64];
        float at = 0.f;
        #pragma unroll
        for (int t = 63; t >= 0; --t) {
            float ev = __expf(pe[t]);
            float cn = __expf(pc[t]);
            at += ev + cn;
            float hz = ev / at;            // at > 0 always (sum of exps)
            lg[t] = __logf(1.f - hz + 1e-7f);
        }
        float c = 0.f;
        #pragma unroll
        for (int t = 0; t < 64; ++t) {
            c += lg[t];
            g_KMTB[t * NEX + row] = __float2bfloat16(__expf(c));
        }
    } else {
        const int warp = tid >> 5, lane = tid & 31;
        const int row = (blk - KM_BLOCKS) * 8 + warp;
        const float4* Ev = reinterpret_cast<const float4*>(E);
        float4 v = Ev[row * (DE / 4) + lane];
        uint2 pk;
        pk.x = pack_bf16x2(v.x, v.y);
        pk.y = pack_bf16x2(v.z, v.w);
        *reinterpret_cast<uint2*>(reinterpret_cast<char*>(g_EB) + row * 256 + lane * 8) = pk;
        float s = v.x * v.x + v.y * v.y + v.z * v.z + v.w * v.w;
        #pragma unroll
        for (int o = 16; o; o >>= 1) s += __shfl_xor_sync(0xffffffffu, s, o);
        if (lane == 0) g_en[row] = s;
    }
}

// ---------------- main mma.sync kernel (R11 shape, lean epilogue) ----------------
// grid (64, 4), 256 threads (8 warps), 2 CTAs/SM (4 warps per SMSP).
// Warp w owns m16 rows. Per 64-exemplar tile, two 32-wide halves:
//   half h: GEMM1 m16 x n32 (K=128) -> epilogue -> GEMM2 K32 into acc2.
#define SM_A    0
#define SM_E    34816
#define SM_KM   69632
#define SM_EN   88064
#define SM_BYTES 88576
#define PITCH_AB 272
#define PITCH_K  144
#define NTILE    64
#define NT_CTA   (NEX / NSPLIT / NTILE)   // 64

__device__ __forceinline__ void prefetch_tile(char* smem, int nb, int buf, int tid) {
    #pragma unroll
    for (int i = 0; i < 4; ++i) {
        int f = tid + i * 256;
        int n = f >> 4, c = f & 15;
        cp_async16(smem + SM_E + buf * 17408 + n * PITCH_AB + c * 16,
                   reinterpret_cast<const char*>(g_EB) + (nb + n) * 256 + c * 16);
    }
    #pragma unroll
    for (int i = 0; i < 2; ++i) {
        int f = tid + i * 256;
        int d = f >> 3, c = f & 7;
        cp_async16(smem + SM_KM + buf * 9216 + d * PITCH_K + c * 16,
                   reinterpret_cast<const char*>(g_KMTB) + d * (NEX * 2) + nb * 2 + c * 16);
    }
    if (tid < 16)
        cp_async16(smem + SM_EN + buf * 256 + tid * 16, g_en + nb + tid * 4);
}

__global__ void __launch_bounds__(256, 2)
main_mma() {
    extern __shared__ __align__(16) char smem[];
    const uint32_t sbase = (uint32_t)__cvta_generic_to_shared(smem);
    const int tid = threadIdx.x;
    const int w = tid >> 5, lane = tid & 31;
    const int g = lane >> 2, tg = lane & 3;
    const int bm = blockIdx.x;
    const int split = blockIdx.y;
    const int nbase0 = split * (NEX / NSPLIT);

    const uint32_t a_lane = (uint32_t)((w * 16 + ((lane >> 3) & 1) * 8 + (lane & 7)) * PITCH_AB
                                       + (lane >> 4) * 16);
    const uint32_t b_laneAB = (uint32_t)(((lane >> 4) * 8 + (lane & 7)) * PITCH_AB
                                         + ((lane >> 3) & 1) * 16);
    const uint32_t b_laneK  = (uint32_t)(((lane >> 4) * 8 + (lane & 7)) * PITCH_K
                                         + ((lane >> 3) & 1) * 16);

    // ---- prologue: A tile + tile 0 ----
    #pragma unroll
    for (int i = 0; i < 8; ++i) {
        int f = tid + i * 256;
        int m = f >> 4, c = f & 15;
        cp_async16(smem + SM_A + m * PITCH_AB + c * 16,
                   reinterpret_cast<const char*>(g_phiB) + (bm * 128 + m) * 256 + c * 16);
    }
    prefetch_tile(smem, nbase0, 0, tid);
    CP_COMMIT();

    // pn pre-scaled by -log2e so the exp argument is one FFMA from (en+acc)
    const float pnl0 = g_pn[bm * 128 + w * 16 + g] * NEG_L2E;
    const float pnl1 = g_pn[bm * 128 + w * 16 + g + 8] * NEG_L2E;

    float acc2[8][4];
    #pragma unroll
    for (int j = 0; j < 8; ++j)
        #pragma unroll
        for (int c = 0; c < 4; ++c) acc2[j][c] = 0.f;
    float dAcc0 = 0.f, dAcc1 = 0.f;

    for (int t = 0; t < NT_CTA; ++t) {
        const int buf = t & 1;
        CP_WAIT0();
        __syncthreads();
        if (t + 1 < NT_CTA) {
            prefetch_tile(smem, nbase0 + (t + 1) * NTILE, buf ^ 1, tid);
            CP_COMMIT();
        }

        const uint32_t AsB = sbase + SM_A + a_lane;
        const uint32_t EsB = sbase + SM_E + buf * 17408 + b_laneAB;
        const uint32_t MsB = sbase + SM_KM + buf * 9216 + b_laneK;
        const float* enb = reinterpret_cast<const float*>(smem + SM_EN + buf * 256);

        #pragma unroll
        for (int h = 0; h < 2; ++h) {
            // ---- GEMM1 half: S = (-2phi) . E^T  (m16 x n32, K=128) ----
            float acc1[4][4];
            #pragma unroll
            for (int j = 0; j < 4; ++j)
                #pragma unroll
                for (int c = 0; c < 4; ++c) acc1[j][c] = 0.f;

            const uint32_t EsH = EsB + (uint32_t)(h * 32) * PITCH_AB;
            #pragma unroll
            for (int kk = 0; kk < 8; ++kk) {
                uint32_t a0, a1, a2, a3;
                ldmat4(a0, a1, a2, a3, AsB + kk * 32);
                uint32_t b0, b1, b2, b3;
                ldmat4(b0, b1, b2, b3, EsH + kk * 32);                  // j=0,1
                uint32_t b4, b5, b6, b7;
                ldmat4(b4, b5, b6, b7, EsH + 16 * PITCH_AB + kk * 32);  // j=2,3
                mma_bf16(acc1[0][0], acc1[0][1], acc1[0][2], acc1[0][3],
                         a0, a1, a2, a3, b0, b1);
                mma_bf16(acc1[1][0], acc1[1][1], acc1[1][2], acc1[1][3],
                         a0, a1, a2, a3, b2, b3);
                mma_bf16(acc1[2][0], acc1[2][1], acc1[2][2], acc1[2][3],
                         a0, a1, a2, a3, b4, b5);
                mma_bf16(acc1[3][0], acc1[3][1], acc1[3][2], acc1[3][3],
                         a0, a1, a2, a3, b6, b7);
            }

            // ---- epilogue: arg = -log2e*d2 via 1 FADD + 1 FFMA; kw = (arg>=-log2e)?EX2:0 ----
            uint32_t kwreg[4][2];
            #pragma unroll
            for (int j = 0; j < 4; ++j) {
                float2 en2 = *reinterpret_cast<const float2*>(enb + h * 32 + j * 8 + 2 * tg);
                float a00 = fmaf(en2.x + acc1[j][0], NEG_L2E, pnl0);
                float a01 = fmaf(en2.y + acc1[j][1], NEG_L2E, pnl0);
                float a10 = fmaf(en2.x + acc1[j][2], NEG_L2E, pnl1);
                float a11 = fmaf(en2.y + acc1[j][3], NEG_L2E, pnl1);
                float k00 = (a00 >= NEG_L2E) ? ex2f(a00) : 0.f;
                float k01 = (a01 >= NEG_L2E) ? ex2f(a01) : 0.f;
                float k10 = (a10 >= NEG_L2E) ? ex2f(a10) : 0.f;
                float k11 = (a11 >= NEG_L2E) ? ex2f(a11) : 0.f;
                dAcc0 += k00 + k01;
                dAcc1 += k10 + k11;
                kwreg[j][0] = pack_bf16x2(k00, k01);
                kwreg[j][1] = pack_bf16x2(k10, k11);
            }

            // ---- GEMM2 half: numer += kw . KM  (m16 x d64, K=32) ----
            #pragma unroll
            for (int q = 0; q < 2; ++q) {
                const int kk2 = h * 2 + q;
                uint32_t b[8][2];
                #pragma unroll
                for (int bj = 0; bj < 4; ++bj)
                    ldmat4(b[2 * bj][0], b[2 * bj][1], b[2 * bj + 1][0], b[2 * bj + 1][1],
                           MsB + bj * 16 * PITCH_K + kk2 * 32);
                const uint32_t a0 = kwreg[2 * q][0], a1 = kwreg[2 * q][1];
                const uint32_t a2 = kwreg[2 * q + 1][0], a3 = kwreg[2 * q + 1][1];
                #pragma unroll
                for (int j = 0; j < 8; ++j)
                    mma_bf16(acc2[j][0], acc2[j][1], acc2[j][2], acc2[j][3],
                             a0, a1, a2, a3, b[j][0], b[j][1]);
            }
        }
    }

    // ---- write numerators ----
    #pragma unroll
    for (int j = 0; j < 8; ++j) {
        const int m_loc = w * 16 + g;
        const int d_loc = j * 8 + 2 * tg;
        float* dst = g_pnum + (size_t)(split * B_N + bm * 128 + m_loc) * NDUR + d_loc;
        *reinterpret_cast<float2*>(dst) = make_float2(acc2[j][0], acc2[j][1]);
        *reinterpret_cast<float2*>(dst + 8 * NDUR) = make_float2(acc2[j][2], acc2[j][3]);
    }

    // ---- denom: quad reduce ----
    dAcc0 += __shfl_xor_sync(0xffffffffu, dAcc0, 1);
    dAcc0 += __shfl_xor_sync(0xffffffffu, dAcc0, 2);
    dAcc1 += __shfl_xor_sync(0xffffffffu, dAcc1, 1);
    dAcc1 += __shfl_xor_sync(0xffffffffu, dAcc1, 2);
    if (tg == 0) {
        g_pden[split * B_N + bm * 128 + w * 16 + g] = dAcc0;
        g_pden[split * B_N + bm * 128 + w * 16 + g + 8] = dAcc1;
    }
}

// ---------------- finalize (with inline baseline-hazard scan) ----------------
__global__ void __launch_bounds__(256)
finalize_kernel(float* __restrict__ out, const float* __restrict__ lh) {
    __shared__ float gb[64];
    const int tid = threadIdx.x;
    if (tid < 64) {
        float h = 1.f / (1.f + __expf(-lh[tid]));
        gb[tid] = __logf(1.f - h + 1e-7f);
    }
    float c = 0.f;
    #pragma unroll
    for (int off = 1; off < 64; off <<= 1) {
        __syncthreads();
        if (tid < 64) c = gb[tid] + ((tid >= off) ? gb[tid - off] : 0.f);
        __syncthreads();
        if (tid < 64) gb[tid] = c;
    }
    __syncthreads();
    const int idx = blockIdx.x * 256 + tid;
    const int b = idx >> 6, d = idx & 63;
    float num = GAMMA_N * __expf(gb[d]);
    float den = GAMMA_N + 1e-12f;
    #pragma unroll
    for (int s = 0; s < NSPLIT; ++s) {
        num += g_pnum[s * B_N * NDUR + idx];
        den += g_pden[s * B_N + b];
    }
    float r = num / den;
    r = fminf(fmaxf(r, 1e-12f), 1.0f - 1e-12f);
    out[idx] = r;
}

// ---------------- launch ----------------
extern "C" void kernel_launch(void* const* d_in, const int* in_sizes, int n_in,
                              void* d_out, int out_size) {
    const float* x    = (const float*)d_in[0];
    const float* W    = (const float*)d_in[1];
    const float* bias = (const float*)d_in[2];
    const float* E    = (const float*)d_in[3];
    const float* lev  = (const float*)d_in[4];
    const float* lcen = (const float*)d_in[5];
    const float* lh   = (const float*)d_in[6];
    float* out = (float*)d_out;

    static bool attr_set = false;
    if (!attr_set) {
        cudaFuncSetAttribute(main_mma,
                             cudaFuncAttributeMaxDynamicSharedMemorySize, SM_BYTES);
        attr_set = true;
    }

    phi_pn_kernel<<<B_N / 16, 128>>>(x, W, bias);
    enkm_kernel<<<KM_BLOCKS + EN_BLOCKS, 256>>>(E, lev, lcen);
    main_mma<<<dim3(B_N / 128, NSPLIT), 256, SM_BYTES>>>();
    finalize_kernel<<<(B_N * NDUR) / 256, 256>>>(out, lh);
}